// round 15
// baseline (speedup 1.0000x reference)
#include <cuda_runtime.h>
#include <cuda_fp16.h>
#include <math.h>

#define BATCH 4
#define SEQ 2048
#define DMODEL 1024
#define NHEADS 16
#define DK 64
#define MTOT (BATCH * SEQ)   // 8192

// Scratch (module-load allocated). All packed fp16, indexed in uint (half2) words.
__device__ unsigned g_xpack[(size_t)MTOT / 128 * 32 * 2048];         // A-frag16 k32 tiles
__device__ unsigned g_wqkv_pack[(size_t)3 * DMODEL / 128 * 32 * 2048]; // B-frag16
__device__ unsigned g_wo_pack[(size_t)DMODEL / 128 * 32 * 2048];
__device__ unsigned g_qpack[(size_t)BATCH * NHEADS * 16 * 4096];     // Q A-frag64
__device__ unsigned g_kpack[(size_t)BATCH * NHEADS * 32 * 2048];     // K B-frag64
__device__ unsigned g_vpack[(size_t)BATCH * NHEADS * 32 * 2048];     // V^T B-frag64
__device__ unsigned g_attn_pack[(size_t)MTOT / 128 * 32 * 2048];     // A-frag16 k32

// ---------------------------------------------------------------------------
// Helpers
// ---------------------------------------------------------------------------
__device__ __forceinline__ unsigned pack_h2(float lo, float hi) {
    __half2 h = __floats2half2_rn(lo, hi);
    return *(unsigned*)&h;
}

__device__ __forceinline__ void mma16(float* c, const unsigned* a, const unsigned* b) {
    asm volatile(
        "mma.sync.aligned.m16n8k16.row.col.f32.f16.f16.f32 "
        "{%0,%1,%2,%3},{%4,%5,%6,%7},{%8,%9},{%0,%1,%2,%3};"
        : "+f"(c[0]), "+f"(c[1]), "+f"(c[2]), "+f"(c[3])
        : "r"(a[0]), "r"(a[1]), "r"(a[2]), "r"(a[3]), "r"(b[0]), "r"(b[1]));
}

__device__ __forceinline__ void cp_async16(unsigned* smem_ptr, const unsigned* gptr) {
    unsigned sa = (unsigned)__cvta_generic_to_shared(smem_ptr);
    asm volatile("cp.async.cg.shared.global [%0], [%1], 16;" :: "r"(sa), "l"(gptr));
}
__device__ __forceinline__ void cp_commit() {
    asm volatile("cp.async.commit_group;");
}

// --- fp16 fragment layouts (word = uint = half2) ---
__device__ __forceinline__ int a_w16(int r, int k) {
    return ((r >> 4) * 2 + (k >> 4)) * 128 + ((r & 7) * 4 + ((k >> 1) & 3)) * 4 +
           (((r >> 3) & 1) | (((k >> 3) & 1) << 1));
}
__device__ __forceinline__ int b_w16(int n, int k) {
    return ((n >> 3) * 2 + (k >> 4)) * 64 + ((n & 7) * 4 + ((k >> 1) & 3)) * 2 +
           ((k >> 3) & 1);
}
__device__ __forceinline__ int aw64h(int r, int d) {
    return ((r >> 4) * 4 + (d >> 4)) * 128 + ((r & 7) * 4 + ((d >> 1) & 3)) * 4 +
           (((r >> 3) & 1) | (((d >> 3) & 1) << 1));
}
__device__ __forceinline__ int bw64h(int n, int k) {
    return ((n >> 3) * 4 + (k >> 4)) * 64 + ((n & 7) * 4 + ((k >> 1) & 3)) * 2 +
           ((k >> 3) & 1);
}

// ---------------------------------------------------------------------------
// Merged prep kernel: packs x (A-frag), w_qkv (B-frag), w_o (B-frag). K=1024.
// ---------------------------------------------------------------------------
#define PA  (MTOT * 256)
#define PB1 (3 * DMODEL * 256)
#define PB2 (DMODEL * 256)

__global__ void prep_kernel(const float* __restrict__ x,
                            const float* __restrict__ wqkv,
                            const float* __restrict__ wo,
                            unsigned* __restrict__ xp,
                            unsigned* __restrict__ wqp,
                            unsigned* __restrict__ wop) {
    int idx = blockIdx.x * blockDim.x + threadIdx.x;
    if (idx < PA) {
        int rg = idx >> 8, c0 = (idx & 255) << 2;
        float4 v = *(const float4*)&x[(size_t)rg * 1024 + c0];
        size_t tile = ((size_t)(rg >> 7) * 32 + (c0 >> 5)) * 2048;
        int r = rg & 127, kl = c0 & 31;
        xp[tile + a_w16(r, kl)]     = pack_h2(v.x, v.y);
        xp[tile + a_w16(r, kl + 2)] = pack_h2(v.z, v.w);
    } else if (idx < PA + PB1) {
        int j = idx - PA;
        int ng = j >> 8, c0 = (j & 255) << 2;
        float4 v = *(const float4*)&wqkv[(size_t)ng * 1024 + c0];
        size_t tile = ((size_t)(ng >> 7) * 32 + (c0 >> 5)) * 2048;
        int n = ng & 127, kl = c0 & 31;
        wqp[tile + b_w16(n, kl)]     = pack_h2(v.x, v.y);
        wqp[tile + b_w16(n, kl + 2)] = pack_h2(v.z, v.w);
    } else if (idx < PA + PB1 + PB2) {
        int j = idx - PA - PB1;
        int ng = j >> 8, c0 = (j & 255) << 2;
        float4 v = *(const float4*)&wo[(size_t)ng * 1024 + c0];
        size_t tile = ((size_t)(ng >> 7) * 32 + (c0 >> 5)) * 2048;
        int n = ng & 127, kl = c0 & 31;
        wop[tile + b_w16(n, kl)]     = pack_h2(v.x, v.y);
        wop[tile + b_w16(n, kl + 2)] = pack_h2(v.z, v.w);
    }
}

// ---------------------------------------------------------------------------
// GEMM mainloop: 64(M) x 128(N) tile, BK=64 stages, 256 threads
// (8 warps: 4 in M x 2 in N, warp tile 16x64). 3-stage ring (24KB/stage),
// one barrier per 64-k stage. 3 CTAs/SM (72KB smem, <=85 regs).
// Stage: [A 64x64 (2x1024 w) | B 128x64 (2x2048 w)] = 6144 words.
// A operand: 64-row slice = half of a 128-row pack tile (rows [0,64) are the
// first 1024 words of each 2048-word k-tile; Ahalf carries the half offset).
// ---------------------------------------------------------------------------
#define GEMM_SMEM (3 * 6144 * 4)   // 72 KB

__device__ __forceinline__ void issue_stage64(unsigned* smbase,
                                              const unsigned* __restrict__ Ahalf,
                                              const unsigned* __restrict__ Bp,
                                              int kt64, int tid) {
    // A: two 1024-word half-slices (k-tiles 2*kt64, 2*kt64+1)
    {
        int c = tid * 4;   // 0..1020
        cp_async16(smbase + c, Ahalf + (size_t)(2 * kt64) * 2048 + c);
        cp_async16(smbase + 1024 + c, Ahalf + (size_t)(2 * kt64 + 1) * 2048 + c);
    }
    // B: contiguous 4096 words
    const unsigned* gb = Bp + (size_t)kt64 * 4096;
#pragma unroll
    for (int i = 0; i < 4; i++) {
        int c = (tid + i * 256) * 4;
        cp_async16(smbase + 2048 + c, gb + c);
    }
}

__device__ __forceinline__ void gemm_mainloop(
    const unsigned* __restrict__ Ahalf, const unsigned* __restrict__ Bp,
    unsigned* sm, int KT64, int tid, int lane, int wm, int wn,
    float acc[8][4]) {
#pragma unroll
    for (int nt = 0; nt < 8; nt++)
#pragma unroll
        for (int e = 0; e < 4; e++) acc[nt][e] = 0.f;

    issue_stage64(sm, Ahalf, Bp, 0, tid); cp_commit();
    issue_stage64(sm + 6144, Ahalf, Bp, 1, tid); cp_commit();

    for (int kt = 0; kt < KT64; kt++) {
        asm volatile("cp.async.wait_group 1;");
        __syncthreads();
        if (kt + 2 < KT64)
            issue_stage64(sm + ((kt + 2) % 3) * 6144, Ahalf, Bp, kt + 2, tid);
        cp_commit();

        const unsigned* As = sm + (kt % 3) * 6144;
        const unsigned* Bs = As + 2048;
#pragma unroll
        for (int ks = 0; ks < 4; ks++) {
            const unsigned* At = As + (ks >> 1) * 1024;
            const unsigned* Bt = Bs + (ks >> 1) * 2048;
            const int kss = ks & 1;
            unsigned af[4], bf[8][2];
            *(uint4*)af = *(const uint4*)&At[(wm * 2 + kss) * 128 + lane * 4];
#pragma unroll
            for (int nt = 0; nt < 8; nt++)
                *(uint2*)bf[nt] = *(const uint2*)
                    &Bt[((wn * 8 + nt) * 2 + kss) * 64 + lane * 2];
#pragma unroll
            for (int nt = 0; nt < 8; nt++)
                mma16(acc[nt], af, bf[nt]);
        }
    }
}

// ---------------------------------------------------------------------------
// Out-proj GEMM: fp32 row-major C. Grid (N/128, M/64).
// ---------------------------------------------------------------------------
__global__ __launch_bounds__(256, 3)
void gemm_packed(const unsigned* __restrict__ Apack, const unsigned* __restrict__ Bpack,
                 float* __restrict__ C, int M, int N, int K) {
    extern __shared__ unsigned sm[];
    const int tid = threadIdx.x;
    const int lane = tid & 31, wid = tid >> 5;
    const int wm = wid & 3, wn = wid >> 2;
    const int KT64 = K >> 6;

    const int my = blockIdx.y;   // 64-row panel
    const unsigned* Ahalf = Apack + (size_t)(my >> 1) * (K >> 5) * 2048 +
                            (size_t)(my & 1) * 1024;
    const unsigned* Bp = Bpack + (size_t)blockIdx.x * (K >> 5) * 2048;

    float acc[8][4];
    gemm_mainloop(Ahalf, Bp, sm, KT64, tid, lane, wm, wn, acc);

    const int row0 = my * 64, col0 = blockIdx.x * 128;
    int r = row0 + wm * 16 + (lane >> 2);
#pragma unroll
    for (int nt = 0; nt < 8; nt++) {
        int cc = col0 + wn * 64 + nt * 8 + 2 * (lane & 3);
        *(float2*)&C[(size_t)r * N + cc] = make_float2(acc[nt][0], acc[nt][1]);
        *(float2*)&C[(size_t)(r + 8) * N + cc] = make_float2(acc[nt][2], acc[nt][3]);
    }
}

// ---------------------------------------------------------------------------
// QKV GEMM + fused RoPE + flash-layout fp16 packing. Grid (24, 128).
// ---------------------------------------------------------------------------
__global__ __launch_bounds__(256, 3)
void gemm_qkv_rope(const unsigned* __restrict__ Apack, const unsigned* __restrict__ Bpack,
                   const int* __restrict__ pos,
                   unsigned* __restrict__ qp, unsigned* __restrict__ kpk,
                   unsigned* __restrict__ vp) {
    extern __shared__ unsigned sm[];
    const int tid = threadIdx.x;
    const int lane = tid & 31, wid = tid >> 5;
    const int wm = wid & 3, wn = wid >> 2;

    const int my = blockIdx.y;   // 64-row panel
    const unsigned* Ahalf = Apack + (size_t)(my >> 1) * 32 * 2048 +
                            (size_t)(my & 1) * 1024;
    const unsigned* Bp = Bpack + (size_t)blockIdx.x * 32 * 2048;

    float acc[8][4];
    gemm_mainloop(Ahalf, Bp, sm, DMODEL >> 6, tid, lane, wm, wn, acc);

    __half* vph = (__half*)vp;
    const int row0 = my * 64, col0 = blockIdx.x * 128;
#pragma unroll
    for (int nt = 0; nt < 8; nt++) {
        int cg = col0 + wn * 64 + nt * 8 + 2 * (lane & 3);   // even
        int which = cg >> 10;
        int hh = (cg & 1023) >> 6;
        int d = cg & 63;                                      // even
#pragma unroll
        for (int half = 0; half < 2; half++) {
            int r = row0 + wm * 16 + (lane >> 2) + half * 8;
            int b = r >> 11, sq = r & 2047;
            float v0 = acc[nt][2 * half];
            float v1 = acc[nt][2 * half + 1];
            if (which < 2) {
                float p = (float)pos[r];
                float inv = exp2f((float)d * -0.20762050593046f);
                float ang = p * inv, sn, cs;
                sincosf(ang, &sn, &cs);
                float r0 = v0 * cs - v1 * sn;
                float r1 = v0 * sn + v1 * cs;
                if (which == 0) {
                    size_t base = ((size_t)(b * NHEADS + hh) * 16 + (sq >> 7)) * 4096;
                    qp[base + aw64h(sq & 127, d)] =
                        pack_h2(r0 * 0.125f, r1 * 0.125f);
                } else {
                    size_t base = ((size_t)(b * NHEADS + hh) * 32 + (sq >> 6)) * 2048;
                    kpk[base + bw64h(sq & 63, d)] = pack_h2(r0, r1);
                }
            } else {
                size_t base = ((size_t)(b * NHEADS + hh) * 32 + (sq >> 6)) * 2048;
                int kk = sq & 63;
                vph[(base + bw64h(d, kk)) * 2 + (kk & 1)]     = __float2half_rn(v0);
                vph[(base + bw64h(d + 1, kk)) * 2 + (kk & 1)] = __float2half_rn(v1);
            }
        }
    }
}

// ---------------------------------------------------------------------------
// Causal flash attention (unchanged from 332us best).
// ---------------------------------------------------------------------------
#define FL_SMEM ((4096 + 6 * 4096) * 4)   // 112 KB

__global__ __launch_bounds__(256, 2)
void flash_packed(const unsigned* __restrict__ Qp, const unsigned* __restrict__ Kp,
                  const unsigned* __restrict__ Vp, unsigned* __restrict__ outp) {
    extern __shared__ unsigned sm[];
    unsigned* Qs = sm;
    unsigned* St = sm + 4096;

    const int bh = blockIdx.x;
    const int hh = bh & (NHEADS - 1);
    const int b  = bh >> 4;
    const int qb = gridDim.y - 1 - blockIdx.y;
    const int q0 = qb * 128;
    const int tid = threadIdx.x;
    const int lane = tid & 31, w = tid >> 5;
    const int qlane = lane & 3, grp = lane >> 2;

    const unsigned* qg = Qp + ((size_t)bh * 16 + qb) * 4096;
    const unsigned* kg = Kp + ((size_t)bh * 32) * 2048;
    const unsigned* vg = Vp + ((size_t)bh * 32) * 2048;

    const int ktiles = qb * 2 + 2;

#pragma unroll
    for (int i = 0; i < 4; i++) {
        int c = (tid + i * 256) * 4;
        cp_async16(Qs + c, qg + c);
    }
#pragma unroll
    for (int t = 0; t < 4; t++) {
        if (t < ktiles) {
            const unsigned* kgn = kg + (size_t)t * 2048;
            const unsigned* vgn = vg + (size_t)t * 2048;
            unsigned* dst = St + t * 4096;
#pragma unroll
            for (int i = 0; i < 2; i++) {
                int c = (tid + i * 256) * 4;
                cp_async16(dst + c, kgn + c);
                cp_async16(dst + 2048 + c, vgn + c);
            }
        }
        cp_commit();
    }

    float o[8][4];
#pragma unroll
    for (int nt = 0; nt < 8; nt++)
#pragma unroll
        for (int e = 0; e < 4; e++) o[nt][e] = 0.f;
    float m_run[2] = {-1e30f, -1e30f};
    float l_run[2] = {0.f, 0.f};

    const int rloc = w * 16 + grp;

    for (int kt = 0; kt < ktiles; kt += 2) {
        asm volatile("cp.async.wait_group 2;");
        __syncthreads();

#pragma unroll
        for (int t = 0; t < 2; t++) {
            int nk = kt + 4 + t;
            if (nk < ktiles) {
                const unsigned* kgn = kg + (size_t)nk * 2048;
                const unsigned* vgn = vg + (size_t)nk * 2048;
                unsigned* dst = St + (nk % 6) * 4096;
#pragma unroll
                for (int i = 0; i < 2; i++) {
                    int c = (tid + i * 256) * 4;
                    cp_async16(dst + c, kgn + c);
                    cp_async16(dst + 2048 + c, vgn + c);
                }
            }
            cp_commit();
        }

#pragma unroll
        for (int sub = 0; sub < 2; sub++) {
            const int kt2 = kt + sub;
            const int k0 = kt2 * 64;
            const unsigned* Ks = St + (kt2 % 6) * 4096;
            const unsigned* Vs = Ks + 2048;

            if (k0 <= q0 + w * 16 + 15) {
                float s[8][4];
#pragma unroll
                for (int nt = 0; nt < 8; nt++)
#pragma unroll
                    for (int e = 0; e < 4; e++) s[nt][e] = 0.f;

#pragma unroll
                for (int ks = 0; ks < 4; ks++) {
                    unsigned qa[4];
                    *(uint4*)qa = *(const uint4*)&Qs[(w * 4 + ks) * 128 + lane * 4];
#pragma unroll
                    for (int nt = 0; nt < 8; nt++) {
                        unsigned kf[2];
                        *(uint2*)kf = *(const uint2*)&Ks[(nt * 4 + ks) * 64 + lane * 2];
                        mma16(s[nt], qa, kf);
                    }
                }

                if (k0 + 63 > q0 + w * 16) {
                    int i0 = q0 + rloc;
#pragma unroll
                    for (int nt = 0; nt < 8; nt++) {
                        int j0 = k0 + nt * 8 + 2 * qlane;
                        if (j0 > i0)         s[nt][0] = -1e30f;
                        if (j0 + 1 > i0)     s[nt][1] = -1e30f;
                        if (j0 > i0 + 8)     s[nt][2] = -1e30f;
                        if (j0 + 1 > i0 + 8) s[nt][3] = -1e30f;
                    }
                }

                float alpha[2];
#pragma unroll
                for (int hrow = 0; hrow < 2; hrow++) {
                    float mx = -1e30f;
#pragma unroll
                    for (int nt = 0; nt < 8; nt++) {
                        mx = fmaxf(mx, s[nt][2 * hrow]);
                        mx = fmaxf(mx, s[nt][2 * hrow + 1]);
                    }
                    mx = fmaxf(mx, __shfl_xor_sync(0xffffffffu, mx, 1));
                    mx = fmaxf(mx, __shfl_xor_sync(0xffffffffu, mx, 2));
                    float mn = fmaxf(m_run[hrow], mx);
                    alpha[hrow] = __expf(m_run[hrow] - mn);
                    m_run[hrow] = mn;
                    float rs = 0.f;
#pragma unroll
                    for (int nt = 0; nt < 8; nt++) {
                        float p0 = __expf(s[nt][2 * hrow] - mn);
                        float p1 = __expf(s[nt][2 * hrow + 1] - mn);
                        s[nt][2 * hrow] = p0;
                        s[nt][2 * hrow + 1] = p1;
                        rs += p0 + p1;
                    }
                    rs += __shfl_xor_sync(0xffffffffu, rs, 1);
                    rs += __shfl_xor_sync(0xffffffffu, rs, 2);
                    l_run[hrow] = l_run[hrow] * alpha[hrow] + rs;
                }
#pragma unroll
                for (int nt = 0; nt < 8; nt++) {
                    o[nt][0] *= alpha[0]; o[nt][1] *= alpha[0];
                    o[nt][2] *= alpha[1]; o[nt][3] *= alpha[1];
                }

#pragma unroll
                for (int ks = 0; ks < 4; ks++) {
                    unsigned pa[4];
                    pa[0] = pack_h2(s[2 * ks][0],     s[2 * ks][1]);
                    pa[1] = pack_h2(s[2 * ks][2],     s[2 * ks][3]);
                    pa[2] = pack_h2(s[2 * ks + 1][0], s[2 * ks + 1][1]);
                    pa[3] = pack_h2(s[2 * ks + 1][2], s[2 * ks + 1][3]);
#pragma unroll
                    for (int nt = 0; nt < 8; nt++) {
                        unsigned vf[2];
                        *(uint2*)vf = *(const uint2*)&Vs[(nt * 4 + ks) * 64 + lane * 2];
                        mma16(o[nt], pa, vf);
                    }
                }
            }
        }
    }

    float inv0 = 1.f / l_run[0];
    float inv1 = 1.f / l_run[1];
    const int rp = (b * SEQ + q0) >> 7;
#pragma unroll
    for (int nt = 0; nt < 8; nt++) {
        int c = hh * 64 + nt * 8 + 2 * qlane;
        int kp = c >> 5, kl = c & 31;
        size_t tb = ((size_t)rp * 32 + kp) * 2048;
        outp[tb + a_w16(rloc, kl)] =
            pack_h2(o[nt][0] * inv0, o[nt][1] * inv0);
        outp[tb + a_w16(rloc + 8, kl)] =
            pack_h2(o[nt][2] * inv1, o[nt][3] * inv1);
    }
}

// ---------------------------------------------------------------------------
// Launch
// ---------------------------------------------------------------------------
extern "C" void kernel_launch(void* const* d_in, const int* in_sizes, int n_in,
                              void* d_out, int out_size) {
    const float* x     = (const float*)d_in[0];
    const int*   pos   = (const int*)d_in[1];
    const float* w_qkv = (const float*)d_in[2];
    const float* w_o   = (const float*)d_in[3];
    float* out = (float*)d_out;

    unsigned *xp = nullptr, *wqp = nullptr, *wop = nullptr, *ap = nullptr;
    unsigned *qp = nullptr, *kp = nullptr, *vp = nullptr;
    cudaGetSymbolAddress((void**)&xp, g_xpack);
    cudaGetSymbolAddress((void**)&wqp, g_wqkv_pack);
    cudaGetSymbolAddress((void**)&wop, g_wo_pack);
    cudaGetSymbolAddress((void**)&ap, g_attn_pack);
    cudaGetSymbolAddress((void**)&qp, g_qpack);
    cudaGetSymbolAddress((void**)&kp, g_kpack);
    cudaGetSymbolAddress((void**)&vp, g_vpack);

    cudaFuncSetAttribute(gemm_packed,
                         cudaFuncAttributeMaxDynamicSharedMemorySize, GEMM_SMEM);
    cudaFuncSetAttribute(gemm_qkv_rope,
                         cudaFuncAttributeMaxDynamicSharedMemorySize, GEMM_SMEM);
    cudaFuncSetAttribute(flash_packed,
                         cudaFuncAttributeMaxDynamicSharedMemorySize, FL_SMEM);

    // 0) Pack all operands (single merged kernel)
    prep_kernel<<<(PA + PB1 + PB2 + 255) / 256, 256>>>(x, w_qkv, w_o, xp, wqp, wop);

    // 1) QKV projection + fused RoPE + flash-layout packing (64x128 tiles)
    gemm_qkv_rope<<<dim3(3 * DMODEL / 128, MTOT / 64), 256, GEMM_SMEM>>>(
        xp, wqp, pos, qp, kp, vp);

    // 2) Flash attention (LPT grid)
    flash_packed<<<dim3(BATCH * NHEADS, SEQ / 128), 256, FL_SMEM>>>(qp, kp, vp, ap);

    // 3) Output projection (64x128 tiles)
    gemm_packed<<<dim3(DMODEL / 128, MTOT / 64), 256, GEMM_SMEM>>>(
        ap, wop, out, MTOT, DMODEL, DMODEL);
}

// round 16
// speedup vs baseline: 1.0456x; 1.0456x over previous
#include <cuda_runtime.h>
#include <cuda_fp16.h>
#include <math.h>

#define BATCH 4
#define SEQ 2048
#define DMODEL 1024
#define NHEADS 16
#define DK 64
#define MTOT (BATCH * SEQ)   // 8192

// Scratch (module-load allocated). All packed fp16, indexed in uint (half2) words.
__device__ unsigned g_xpack[(size_t)MTOT / 128 * 32 * 2048];         // A-frag16 k32 tiles
__device__ unsigned g_wqkv_pack[(size_t)3 * DMODEL / 128 * 32 * 2048]; // B-frag16 paired
__device__ unsigned g_wo_pack[(size_t)DMODEL / 128 * 32 * 2048];
__device__ unsigned g_qpack[(size_t)BATCH * NHEADS * 16 * 4096];     // Q A-frag64
__device__ unsigned g_kpack[(size_t)BATCH * NHEADS * 32 * 2048];     // K B-frag64
__device__ unsigned g_vpack[(size_t)BATCH * NHEADS * 32 * 2048];     // V^T B-frag64
__device__ unsigned g_attn_pack[(size_t)MTOT / 128 * 32 * 2048];     // A-frag16 k32

// ---------------------------------------------------------------------------
// Helpers
// ---------------------------------------------------------------------------
__device__ __forceinline__ unsigned pack_h2(float lo, float hi) {
    __half2 h = __floats2half2_rn(lo, hi);
    return *(unsigned*)&h;
}

__device__ __forceinline__ void mma16(float* c, const unsigned* a, const unsigned* b) {
    asm volatile(
        "mma.sync.aligned.m16n8k16.row.col.f32.f16.f16.f32 "
        "{%0,%1,%2,%3},{%4,%5,%6,%7},{%8,%9},{%0,%1,%2,%3};"
        : "+f"(c[0]), "+f"(c[1]), "+f"(c[2]), "+f"(c[3])
        : "r"(a[0]), "r"(a[1]), "r"(a[2]), "r"(a[3]), "r"(b[0]), "r"(b[1]));
}

__device__ __forceinline__ void cp_async16(unsigned* smem_ptr, const unsigned* gptr) {
    unsigned sa = (unsigned)__cvta_generic_to_shared(smem_ptr);
    asm volatile("cp.async.cg.shared.global [%0], [%1], 16;" :: "r"(sa), "l"(gptr));
}
__device__ __forceinline__ void cp_commit() {
    asm volatile("cp.async.commit_group;");
}

// --- fp16 fragment layouts (word = uint = half2) ---
// GEMM A, 128x32 k-tile (2048 w): unchanged.
__device__ __forceinline__ int a_w16(int r, int k) {
    return ((r >> 4) * 2 + (k >> 4)) * 128 + ((r & 7) * 4 + ((k >> 1) & 3)) * 4 +
           (((r >> 3) & 1) | (((k >> 3) & 1) << 1));
}
// GEMM B, 128x32 k-tile, nt-PAIRED (2048 w): pair = (n>>4, k16); within a pair,
// word = pair*128 + lane*4 + reg, reg = ((n>>3)&1)*2 + ((k>>3)&1).
// One LDS.128 -> B frags for nt even (xy) and nt odd (zw).
__device__ __forceinline__ int b_w16p(int n, int k) {
    return ((n >> 4) * 2 + (k >> 4)) * 128 + ((n & 7) * 4 + ((k >> 1) & 3)) * 4 +
           (((n >> 3) & 1) << 1) + ((k >> 3) & 1);
}
// Flash layouts (unchanged).
__device__ __forceinline__ int aw64h(int r, int d) {
    return ((r >> 4) * 4 + (d >> 4)) * 128 + ((r & 7) * 4 + ((d >> 1) & 3)) * 4 +
           (((r >> 3) & 1) | (((d >> 3) & 1) << 1));
}
__device__ __forceinline__ int bw64h(int n, int k) {
    return ((n >> 3) * 4 + (k >> 4)) * 64 + ((n & 7) * 4 + ((k >> 1) & 3)) * 2 +
           ((k >> 3) & 1);
}

// ---------------------------------------------------------------------------
// Merged prep kernel: packs x (A-frag), w_qkv / w_o (B-frag paired). K=1024.
// ---------------------------------------------------------------------------
#define PA  (MTOT * 256)
#define PB1 (3 * DMODEL * 256)
#define PB2 (DMODEL * 256)

__global__ void prep_kernel(const float* __restrict__ x,
                            const float* __restrict__ wqkv,
                            const float* __restrict__ wo,
                            unsigned* __restrict__ xp,
                            unsigned* __restrict__ wqp,
                            unsigned* __restrict__ wop) {
    int idx = blockIdx.x * blockDim.x + threadIdx.x;
    if (idx < PA) {
        int rg = idx >> 8, c0 = (idx & 255) << 2;
        float4 v = *(const float4*)&x[(size_t)rg * 1024 + c0];
        size_t tile = ((size_t)(rg >> 7) * 32 + (c0 >> 5)) * 2048;
        int r = rg & 127, kl = c0 & 31;
        xp[tile + a_w16(r, kl)]     = pack_h2(v.x, v.y);
        xp[tile + a_w16(r, kl + 2)] = pack_h2(v.z, v.w);
    } else if (idx < PA + PB1) {
        int j = idx - PA;
        int ng = j >> 8, c0 = (j & 255) << 2;
        float4 v = *(const float4*)&wqkv[(size_t)ng * 1024 + c0];
        size_t tile = ((size_t)(ng >> 7) * 32 + (c0 >> 5)) * 2048;
        int n = ng & 127, kl = c0 & 31;
        wqp[tile + b_w16p(n, kl)]     = pack_h2(v.x, v.y);
        wqp[tile + b_w16p(n, kl + 2)] = pack_h2(v.z, v.w);
    } else if (idx < PA + PB1 + PB2) {
        int j = idx - PA - PB1;
        int ng = j >> 8, c0 = (j & 255) << 2;
        float4 v = *(const float4*)&wo[(size_t)ng * 1024 + c0];
        size_t tile = ((size_t)(ng >> 7) * 32 + (c0 >> 5)) * 2048;
        int n = ng & 127, kl = c0 & 31;
        wop[tile + b_w16p(n, kl)]     = pack_h2(v.x, v.y);
        wop[tile + b_w16p(n, kl + 2)] = pack_h2(v.z, v.w);
    }
}

// ---------------------------------------------------------------------------
// GEMM mainloop: 128x128 tile, BK=64 stages, 256 threads (8 warps 4x2),
// warp 32x64. 3-stage ring (32KB/stage), one barrier per 64-k stage.
// B operands nt-paired: 4 x LDS.128 per ks-step feed 16 mma.
// ---------------------------------------------------------------------------
#define GEMM_SMEM (3 * 8192 * 4)   // 96 KB

__device__ __forceinline__ void issue_stage64(unsigned* smbase,
                                              const unsigned* __restrict__ Ap,
                                              const unsigned* __restrict__ Bp,
                                              int kt64, int tid) {
    const unsigned* ga = Ap + (size_t)kt64 * 4096;
    const unsigned* gb = Bp + (size_t)kt64 * 4096;
#pragma unroll
    for (int i = 0; i < 4; i++) {
        int c = (tid + i * 256) * 4;
        cp_async16(smbase + c, ga + c);
        cp_async16(smbase + 4096 + c, gb + c);
    }
}

__device__ __forceinline__ void gemm_mainloop(
    const unsigned* __restrict__ Ap, const unsigned* __restrict__ Bp,
    unsigned* sm, int KT64, int tid, int lane, int wm, int wn,
    float acc[2][8][4]) {
#pragma unroll
    for (int mt = 0; mt < 2; mt++)
#pragma unroll
        for (int nt = 0; nt < 8; nt++)
#pragma unroll
            for (int e = 0; e < 4; e++) acc[mt][nt][e] = 0.f;

    issue_stage64(sm, Ap, Bp, 0, tid); cp_commit();
    issue_stage64(sm + 8192, Ap, Bp, 1, tid); cp_commit();

    for (int kt = 0; kt < KT64; kt++) {
        asm volatile("cp.async.wait_group 1;");
        __syncthreads();
        if (kt + 2 < KT64)
            issue_stage64(sm + ((kt + 2) % 3) * 8192, Ap, Bp, kt + 2, tid);
        cp_commit();

        const unsigned* As = sm + (kt % 3) * 8192;
        const unsigned* Bs = As + 4096;
#pragma unroll
        for (int ks = 0; ks < 4; ks++) {
            const unsigned* At = As + (ks >> 1) * 2048;
            const unsigned* Bt = Bs + (ks >> 1) * 2048;
            const int kss = ks & 1;
            unsigned af[2][4];
#pragma unroll
            for (int mt = 0; mt < 2; mt++)
                *(uint4*)af[mt] = *(const uint4*)
                    &At[((wm * 2 + mt) * 2 + kss) * 128 + lane * 4];
#pragma unroll
            for (int nt2 = 0; nt2 < 4; nt2++) {
                unsigned bq[4];
                *(uint4*)bq = *(const uint4*)
                    &Bt[(((wn * 4 + nt2) * 2) + kss) * 128 + lane * 4];
#pragma unroll
                for (int mt = 0; mt < 2; mt++) {
                    mma16(acc[mt][2 * nt2],     af[mt], &bq[0]);
                    mma16(acc[mt][2 * nt2 + 1], af[mt], &bq[2]);
                }
            }
        }
    }
}

// ---------------------------------------------------------------------------
// Out-proj GEMM: fp32 row-major C.
// ---------------------------------------------------------------------------
__global__ __launch_bounds__(256, 2)
void gemm_packed(const unsigned* __restrict__ Apack, const unsigned* __restrict__ Bpack,
                 float* __restrict__ C, int M, int N, int K) {
    extern __shared__ unsigned sm[];
    const int tid = threadIdx.x;
    const int lane = tid & 31, wid = tid >> 5;
    const int wm = wid & 3, wn = wid >> 2;
    const int KT64 = K >> 6;

    const unsigned* Ap = Apack + (size_t)blockIdx.y * (K >> 5) * 2048;
    const unsigned* Bp = Bpack + (size_t)blockIdx.x * (K >> 5) * 2048;

    float acc[2][8][4];
    gemm_mainloop(Ap, Bp, sm, KT64, tid, lane, wm, wn, acc);

    const int row0 = blockIdx.y * 128, col0 = blockIdx.x * 128;
#pragma unroll
    for (int mt = 0; mt < 2; mt++)
#pragma unroll
        for (int nt = 0; nt < 8; nt++) {
            int r = row0 + wm * 32 + mt * 16 + (lane >> 2);
            int cc = col0 + wn * 64 + nt * 8 + 2 * (lane & 3);
            *(float2*)&C[(size_t)r * N + cc] =
                make_float2(acc[mt][nt][0], acc[mt][nt][1]);
            *(float2*)&C[(size_t)(r + 8) * N + cc] =
                make_float2(acc[mt][nt][2], acc[mt][nt][3]);
        }
}

// ---------------------------------------------------------------------------
// QKV GEMM + fused RoPE + flash-layout fp16 packing epilogue.
// ---------------------------------------------------------------------------
__global__ __launch_bounds__(256, 2)
void gemm_qkv_rope(const unsigned* __restrict__ Apack, const unsigned* __restrict__ Bpack,
                   const int* __restrict__ pos,
                   unsigned* __restrict__ qp, unsigned* __restrict__ kpk,
                   unsigned* __restrict__ vp) {
    extern __shared__ unsigned sm[];
    const int tid = threadIdx.x;
    const int lane = tid & 31, wid = tid >> 5;
    const int wm = wid & 3, wn = wid >> 2;

    const unsigned* Ap = Apack + (size_t)blockIdx.y * 32 * 2048;
    const unsigned* Bp = Bpack + (size_t)blockIdx.x * 32 * 2048;

    float acc[2][8][4];
    gemm_mainloop(Ap, Bp, sm, DMODEL >> 6, tid, lane, wm, wn, acc);

    __half* vph = (__half*)vp;
    const int row0 = blockIdx.y * 128, col0 = blockIdx.x * 128;
#pragma unroll
    for (int mt = 0; mt < 2; mt++)
#pragma unroll
        for (int nt = 0; nt < 8; nt++) {
            int cg = col0 + wn * 64 + nt * 8 + 2 * (lane & 3);   // even
            int which = cg >> 10;
            int hh = (cg & 1023) >> 6;
            int d = cg & 63;                                      // even
#pragma unroll
            for (int half = 0; half < 2; half++) {
                int r = row0 + wm * 32 + mt * 16 + (lane >> 2) + half * 8;
                int b = r >> 11, sq = r & 2047;
                float v0 = acc[mt][nt][2 * half];
                float v1 = acc[mt][nt][2 * half + 1];
                if (which < 2) {
                    float p = (float)pos[r];
                    float inv = exp2f((float)d * -0.20762050593046f);
                    float ang = p * inv, sn, cs;
                    sincosf(ang, &sn, &cs);
                    float r0 = v0 * cs - v1 * sn;
                    float r1 = v0 * sn + v1 * cs;
                    if (which == 0) {
                        size_t base = ((size_t)(b * NHEADS + hh) * 16 + (sq >> 7)) * 4096;
                        qp[base + aw64h(sq & 127, d)] =
                            pack_h2(r0 * 0.125f, r1 * 0.125f);
                    } else {
                        size_t base = ((size_t)(b * NHEADS + hh) * 32 + (sq >> 6)) * 2048;
                        kpk[base + bw64h(sq & 63, d)] = pack_h2(r0, r1);
                    }
                } else {
                    size_t base = ((size_t)(b * NHEADS + hh) * 32 + (sq >> 6)) * 2048;
                    int kk = sq & 63;
                    vph[(base + bw64h(d, kk)) * 2 + (kk & 1)]     = __float2half_rn(v0);
                    vph[(base + bw64h(d + 1, kk)) * 2 + (kk & 1)] = __float2half_rn(v1);
                }
            }
        }
}

// ---------------------------------------------------------------------------
// Causal flash attention (unchanged from 332us best; LPT grid).
// ---------------------------------------------------------------------------
#define FL_SMEM ((4096 + 6 * 4096) * 4)   // 112 KB

__global__ __launch_bounds__(256, 2)
void flash_packed(const unsigned* __restrict__ Qp, const unsigned* __restrict__ Kp,
                  const unsigned* __restrict__ Vp, unsigned* __restrict__ outp) {
    extern __shared__ unsigned sm[];
    unsigned* Qs = sm;
    unsigned* St = sm + 4096;

    const int bh = blockIdx.x;
    const int hh = bh & (NHEADS - 1);
    const int b  = bh >> 4;
    const int qb = gridDim.y - 1 - blockIdx.y;
    const int q0 = qb * 128;
    const int tid = threadIdx.x;
    const int lane = tid & 31, w = tid >> 5;
    const int qlane = lane & 3, grp = lane >> 2;

    const unsigned* qg = Qp + ((size_t)bh * 16 + qb) * 4096;
    const unsigned* kg = Kp + ((size_t)bh * 32) * 2048;
    const unsigned* vg = Vp + ((size_t)bh * 32) * 2048;

    const int ktiles = qb * 2 + 2;

#pragma unroll
    for (int i = 0; i < 4; i++) {
        int c = (tid + i * 256) * 4;
        cp_async16(Qs + c, qg + c);
    }
#pragma unroll
    for (int t = 0; t < 4; t++) {
        if (t < ktiles) {
            const unsigned* kgn = kg + (size_t)t * 2048;
            const unsigned* vgn = vg + (size_t)t * 2048;
            unsigned* dst = St + t * 4096;
#pragma unroll
            for (int i = 0; i < 2; i++) {
                int c = (tid + i * 256) * 4;
                cp_async16(dst + c, kgn + c);
                cp_async16(dst + 2048 + c, vgn + c);
            }
        }
        cp_commit();
    }

    float o[8][4];
#pragma unroll
    for (int nt = 0; nt < 8; nt++)
#pragma unroll
        for (int e = 0; e < 4; e++) o[nt][e] = 0.f;
    float m_run[2] = {-1e30f, -1e30f};
    float l_run[2] = {0.f, 0.f};

    const int rloc = w * 16 + grp;

    for (int kt = 0; kt < ktiles; kt += 2) {
        asm volatile("cp.async.wait_group 2;");
        __syncthreads();

#pragma unroll
        for (int t = 0; t < 2; t++) {
            int nk = kt + 4 + t;
            if (nk < ktiles) {
                const unsigned* kgn = kg + (size_t)nk * 2048;
                const unsigned* vgn = vg + (size_t)nk * 2048;
                unsigned* dst = St + (nk % 6) * 4096;
#pragma unroll
                for (int i = 0; i < 2; i++) {
                    int c = (tid + i * 256) * 4;
                    cp_async16(dst + c, kgn + c);
                    cp_async16(dst + 2048 + c, vgn + c);
                }
            }
            cp_commit();
        }

#pragma unroll
        for (int sub = 0; sub < 2; sub++) {
            const int kt2 = kt + sub;
            const int k0 = kt2 * 64;
            const unsigned* Ks = St + (kt2 % 6) * 4096;
            const unsigned* Vs = Ks + 2048;

            if (k0 <= q0 + w * 16 + 15) {
                float s[8][4];
#pragma unroll
                for (int nt = 0; nt < 8; nt++)
#pragma unroll
                    for (int e = 0; e < 4; e++) s[nt][e] = 0.f;

#pragma unroll
                for (int ks = 0; ks < 4; ks++) {
                    unsigned qa[4];
                    *(uint4*)qa = *(const uint4*)&Qs[(w * 4 + ks) * 128 + lane * 4];
#pragma unroll
                    for (int nt = 0; nt < 8; nt++) {
                        unsigned kf[2];
                        *(uint2*)kf = *(const uint2*)&Ks[(nt * 4 + ks) * 64 + lane * 2];
                        mma16(s[nt], qa, kf);
                    }
                }

                if (k0 + 63 > q0 + w * 16) {
                    int i0 = q0 + rloc;
#pragma unroll
                    for (int nt = 0; nt < 8; nt++) {
                        int j0 = k0 + nt * 8 + 2 * qlane;
                        if (j0 > i0)         s[nt][0] = -1e30f;
                        if (j0 + 1 > i0)     s[nt][1] = -1e30f;
                        if (j0 > i0 + 8)     s[nt][2] = -1e30f;
                        if (j0 + 1 > i0 + 8) s[nt][3] = -1e30f;
                    }
                }

                float alpha[2];
#pragma unroll
                for (int hrow = 0; hrow < 2; hrow++) {
                    float mx = -1e30f;
#pragma unroll
                    for (int nt = 0; nt < 8; nt++) {
                        mx = fmaxf(mx, s[nt][2 * hrow]);
                        mx = fmaxf(mx, s[nt][2 * hrow + 1]);
                    }
                    mx = fmaxf(mx, __shfl_xor_sync(0xffffffffu, mx, 1));
                    mx = fmaxf(mx, __shfl_xor_sync(0xffffffffu, mx, 2));
                    float mn = fmaxf(m_run[hrow], mx);
                    alpha[hrow] = __expf(m_run[hrow] - mn);
                    m_run[hrow] = mn;
                    float rs = 0.f;
#pragma unroll
                    for (int nt = 0; nt < 8; nt++) {
                        float p0 = __expf(s[nt][2 * hrow] - mn);
                        float p1 = __expf(s[nt][2 * hrow + 1] - mn);
                        s[nt][2 * hrow] = p0;
                        s[nt][2 * hrow + 1] = p1;
                        rs += p0 + p1;
                    }
                    rs += __shfl_xor_sync(0xffffffffu, rs, 1);
                    rs += __shfl_xor_sync(0xffffffffu, rs, 2);
                    l_run[hrow] = l_run[hrow] * alpha[hrow] + rs;
                }
#pragma unroll
                for (int nt = 0; nt < 8; nt++) {
                    o[nt][0] *= alpha[0]; o[nt][1] *= alpha[0];
                    o[nt][2] *= alpha[1]; o[nt][3] *= alpha[1];
                }

#pragma unroll
                for (int ks = 0; ks < 4; ks++) {
                    unsigned pa[4];
                    pa[0] = pack_h2(s[2 * ks][0],     s[2 * ks][1]);
                    pa[1] = pack_h2(s[2 * ks][2],     s[2 * ks][3]);
                    pa[2] = pack_h2(s[2 * ks + 1][0], s[2 * ks + 1][1]);
                    pa[3] = pack_h2(s[2 * ks + 1][2], s[2 * ks + 1][3]);
#pragma unroll
                    for (int nt = 0; nt < 8; nt++) {
                        unsigned vf[2];
                        *(uint2*)vf = *(const uint2*)&Vs[(nt * 4 + ks) * 64 + lane * 2];
                        mma16(o[nt], pa, vf);
                    }
                }
            }
        }
    }

    float inv0 = 1.f / l_run[0];
    float inv1 = 1.f / l_run[1];
    const int rp = (b * SEQ + q0) >> 7;
#pragma unroll
    for (int nt = 0; nt < 8; nt++) {
        int c = hh * 64 + nt * 8 + 2 * qlane;
        int kp = c >> 5, kl = c & 31;
        size_t tb = ((size_t)rp * 32 + kp) * 2048;
        outp[tb + a_w16(rloc, kl)] =
            pack_h2(o[nt][0] * inv0, o[nt][1] * inv0);
        outp[tb + a_w16(rloc + 8, kl)] =
            pack_h2(o[nt][2] * inv1, o[nt][3] * inv1);
    }
}

// ---------------------------------------------------------------------------
// Launch
// ---------------------------------------------------------------------------
extern "C" void kernel_launch(void* const* d_in, const int* in_sizes, int n_in,
                              void* d_out, int out_size) {
    const float* x     = (const float*)d_in[0];
    const int*   pos   = (const int*)d_in[1];
    const float* w_qkv = (const float*)d_in[2];
    const float* w_o   = (const float*)d_in[3];
    float* out = (float*)d_out;

    unsigned *xp = nullptr, *wqp = nullptr, *wop = nullptr, *ap = nullptr;
    unsigned *qp = nullptr, *kp = nullptr, *vp = nullptr;
    cudaGetSymbolAddress((void**)&xp, g_xpack);
    cudaGetSymbolAddress((void**)&wqp, g_wqkv_pack);
    cudaGetSymbolAddress((void**)&wop, g_wo_pack);
    cudaGetSymbolAddress((void**)&ap, g_attn_pack);
    cudaGetSymbolAddress((void**)&qp, g_qpack);
    cudaGetSymbolAddress((void**)&kp, g_kpack);
    cudaGetSymbolAddress((void**)&vp, g_vpack);

    cudaFuncSetAttribute(gemm_packed,
                         cudaFuncAttributeMaxDynamicSharedMemorySize, GEMM_SMEM);
    cudaFuncSetAttribute(gemm_qkv_rope,
                         cudaFuncAttributeMaxDynamicSharedMemorySize, GEMM_SMEM);
    cudaFuncSetAttribute(flash_packed,
                         cudaFuncAttributeMaxDynamicSharedMemorySize, FL_SMEM);

    // 0) Pack all operands (single merged kernel)
    prep_kernel<<<(PA + PB1 + PB2 + 255) / 256, 256>>>(x, w_qkv, w_o, xp, wqp, wop);

    // 1) QKV projection + fused RoPE + flash-layout packing
    gemm_qkv_rope<<<dim3(3 * DMODEL / 128, MTOT / 128), 256, GEMM_SMEM>>>(
        xp, wqp, pos, qp, kp, vp);

    // 2) Flash attention (LPT grid)
    flash_packed<<<dim3(BATCH * NHEADS, SEQ / 128), 256, FL_SMEM>>>(qp, kp, vp, ap);

    // 3) Output projection
    gemm_packed<<<dim3(DMODEL / 128, MTOT / 128), 256, GEMM_SMEM>>>(
        ap, wop, out, MTOT, DMODEL, DMODEL);
}

// round 17
// speedup vs baseline: 1.0491x; 1.0033x over previous
#include <cuda_runtime.h>
#include <cuda_fp16.h>
#include <math.h>

#define BATCH 4
#define SEQ 2048
#define DMODEL 1024
#define NHEADS 16
#define DK 64
#define MTOT (BATCH * SEQ)   // 8192

// Scratch (module-load allocated). All packed fp16, indexed in uint (half2) words.
__device__ unsigned g_xpack[(size_t)MTOT / 128 * 32 * 2048];         // A-frag16 k32 tiles
__device__ unsigned g_wqkv_pack[(size_t)3 * DMODEL / 128 * 32 * 2048]; // B-frag16 paired
__device__ unsigned g_wo_pack[(size_t)DMODEL / 128 * 32 * 2048];
__device__ unsigned g_qpack[(size_t)BATCH * NHEADS * 16 * 4096];     // Q A-frag64
__device__ unsigned g_kpack[(size_t)BATCH * NHEADS * 32 * 2048];     // K B-frag64 nt-paired
__device__ unsigned g_vpack[(size_t)BATCH * NHEADS * 32 * 2048];     // V^T B-frag64 nt-paired
__device__ unsigned g_attn_pack[(size_t)MTOT / 128 * 32 * 2048];     // A-frag16 k32

// ---------------------------------------------------------------------------
// Helpers
// ---------------------------------------------------------------------------
__device__ __forceinline__ unsigned pack_h2(float lo, float hi) {
    __half2 h = __floats2half2_rn(lo, hi);
    return *(unsigned*)&h;
}

__device__ __forceinline__ void mma16(float* c, const unsigned* a, const unsigned* b) {
    asm volatile(
        "mma.sync.aligned.m16n8k16.row.col.f32.f16.f16.f32 "
        "{%0,%1,%2,%3},{%4,%5,%6,%7},{%8,%9},{%0,%1,%2,%3};"
        : "+f"(c[0]), "+f"(c[1]), "+f"(c[2]), "+f"(c[3])
        : "r"(a[0]), "r"(a[1]), "r"(a[2]), "r"(a[3]), "r"(b[0]), "r"(b[1]));
}

__device__ __forceinline__ void cp_async16(unsigned* smem_ptr, const unsigned* gptr) {
    unsigned sa = (unsigned)__cvta_generic_to_shared(smem_ptr);
    asm volatile("cp.async.cg.shared.global [%0], [%1], 16;" :: "r"(sa), "l"(gptr));
}
__device__ __forceinline__ void cp_commit() {
    asm volatile("cp.async.commit_group;");
}

// --- fp16 fragment layouts (word = uint = half2) ---
// GEMM A, 128x32 k-tile (2048 w).
__device__ __forceinline__ int a_w16(int r, int k) {
    return ((r >> 4) * 2 + (k >> 4)) * 128 + ((r & 7) * 4 + ((k >> 1) & 3)) * 4 +
           (((r >> 3) & 1) | (((k >> 3) & 1) << 1));
}
// GEMM B, 128x32 k-tile, nt-PAIRED (2048 w).
__device__ __forceinline__ int b_w16p(int n, int k) {
    return ((n >> 4) * 2 + (k >> 4)) * 128 + ((n & 7) * 4 + ((k >> 1) & 3)) * 4 +
           (((n >> 3) & 1) << 1) + ((k >> 3) & 1);
}
// Flash Q (A-frag, 128x64 = 4096 w).
__device__ __forceinline__ int aw64h(int r, int d) {
    return ((r >> 4) * 4 + (d >> 4)) * 128 + ((r & 7) * 4 + ((d >> 1) & 3)) * 4 +
           (((r >> 3) & 1) | (((d >> 3) & 1) << 1));
}
// Flash K / V^T (B-frag, 64x64 = 2048 w), nt-PAIRED:
// pair = ((n>>4)*4 + (k>>4)) [16 pairs x 128 w]; reg = ((n>>3)&1)*2 + ((k>>3)&1).
__device__ __forceinline__ int bw64h_p(int n, int k) {
    return ((n >> 4) * 4 + (k >> 4)) * 128 + ((n & 7) * 4 + ((k >> 1) & 3)) * 4 +
           (((n >> 3) & 1) << 1) + ((k >> 3) & 1);
}

// ---------------------------------------------------------------------------
// Merged prep kernel: packs x (A-frag), w_qkv / w_o (B-frag paired). K=1024.
// ---------------------------------------------------------------------------
#define PA  (MTOT * 256)
#define PB1 (3 * DMODEL * 256)
#define PB2 (DMODEL * 256)

__global__ void prep_kernel(const float* __restrict__ x,
                            const float* __restrict__ wqkv,
                            const float* __restrict__ wo,
                            unsigned* __restrict__ xp,
                            unsigned* __restrict__ wqp,
                            unsigned* __restrict__ wop) {
    int idx = blockIdx.x * blockDim.x + threadIdx.x;
    if (idx < PA) {
        int rg = idx >> 8, c0 = (idx & 255) << 2;
        float4 v = *(const float4*)&x[(size_t)rg * 1024 + c0];
        size_t tile = ((size_t)(rg >> 7) * 32 + (c0 >> 5)) * 2048;
        int r = rg & 127, kl = c0 & 31;
        xp[tile + a_w16(r, kl)]     = pack_h2(v.x, v.y);
        xp[tile + a_w16(r, kl + 2)] = pack_h2(v.z, v.w);
    } else if (idx < PA + PB1) {
        int j = idx - PA;
        int ng = j >> 8, c0 = (j & 255) << 2;
        float4 v = *(const float4*)&wqkv[(size_t)ng * 1024 + c0];
        size_t tile = ((size_t)(ng >> 7) * 32 + (c0 >> 5)) * 2048;
        int n = ng & 127, kl = c0 & 31;
        wqp[tile + b_w16p(n, kl)]     = pack_h2(v.x, v.y);
        wqp[tile + b_w16p(n, kl + 2)] = pack_h2(v.z, v.w);
    } else if (idx < PA + PB1 + PB2) {
        int j = idx - PA - PB1;
        int ng = j >> 8, c0 = (j & 255) << 2;
        float4 v = *(const float4*)&wo[(size_t)ng * 1024 + c0];
        size_t tile = ((size_t)(ng >> 7) * 32 + (c0 >> 5)) * 2048;
        int n = ng & 127, kl = c0 & 31;
        wop[tile + b_w16p(n, kl)]     = pack_h2(v.x, v.y);
        wop[tile + b_w16p(n, kl + 2)] = pack_h2(v.z, v.w);
    }
}

// ---------------------------------------------------------------------------
// GEMM mainloop (R16, unchanged): 128x128 tile, BK=64, nt-paired B.
// ---------------------------------------------------------------------------
#define GEMM_SMEM (3 * 8192 * 4)   // 96 KB

__device__ __forceinline__ void issue_stage64(unsigned* smbase,
                                              const unsigned* __restrict__ Ap,
                                              const unsigned* __restrict__ Bp,
                                              int kt64, int tid) {
    const unsigned* ga = Ap + (size_t)kt64 * 4096;
    const unsigned* gb = Bp + (size_t)kt64 * 4096;
#pragma unroll
    for (int i = 0; i < 4; i++) {
        int c = (tid + i * 256) * 4;
        cp_async16(smbase + c, ga + c);
        cp_async16(smbase + 4096 + c, gb + c);
    }
}

__device__ __forceinline__ void gemm_mainloop(
    const unsigned* __restrict__ Ap, const unsigned* __restrict__ Bp,
    unsigned* sm, int KT64, int tid, int lane, int wm, int wn,
    float acc[2][8][4]) {
#pragma unroll
    for (int mt = 0; mt < 2; mt++)
#pragma unroll
        for (int nt = 0; nt < 8; nt++)
#pragma unroll
            for (int e = 0; e < 4; e++) acc[mt][nt][e] = 0.f;

    issue_stage64(sm, Ap, Bp, 0, tid); cp_commit();
    issue_stage64(sm + 8192, Ap, Bp, 1, tid); cp_commit();

    for (int kt = 0; kt < KT64; kt++) {
        asm volatile("cp.async.wait_group 1;");
        __syncthreads();
        if (kt + 2 < KT64)
            issue_stage64(sm + ((kt + 2) % 3) * 8192, Ap, Bp, kt + 2, tid);
        cp_commit();

        const unsigned* As = sm + (kt % 3) * 8192;
        const unsigned* Bs = As + 4096;
#pragma unroll
        for (int ks = 0; ks < 4; ks++) {
            const unsigned* At = As + (ks >> 1) * 2048;
            const unsigned* Bt = Bs + (ks >> 1) * 2048;
            const int kss = ks & 1;
            unsigned af[2][4];
#pragma unroll
            for (int mt = 0; mt < 2; mt++)
                *(uint4*)af[mt] = *(const uint4*)
                    &At[((wm * 2 + mt) * 2 + kss) * 128 + lane * 4];
#pragma unroll
            for (int nt2 = 0; nt2 < 4; nt2++) {
                unsigned bq[4];
                *(uint4*)bq = *(const uint4*)
                    &Bt[(((wn * 4 + nt2) * 2) + kss) * 128 + lane * 4];
#pragma unroll
                for (int mt = 0; mt < 2; mt++) {
                    mma16(acc[mt][2 * nt2],     af[mt], &bq[0]);
                    mma16(acc[mt][2 * nt2 + 1], af[mt], &bq[2]);
                }
            }
        }
    }
}

// ---------------------------------------------------------------------------
// Out-proj GEMM: fp32 row-major C.
// ---------------------------------------------------------------------------
__global__ __launch_bounds__(256, 2)
void gemm_packed(const unsigned* __restrict__ Apack, const unsigned* __restrict__ Bpack,
                 float* __restrict__ C, int M, int N, int K) {
    extern __shared__ unsigned sm[];
    const int tid = threadIdx.x;
    const int lane = tid & 31, wid = tid >> 5;
    const int wm = wid & 3, wn = wid >> 2;
    const int KT64 = K >> 6;

    const unsigned* Ap = Apack + (size_t)blockIdx.y * (K >> 5) * 2048;
    const unsigned* Bp = Bpack + (size_t)blockIdx.x * (K >> 5) * 2048;

    float acc[2][8][4];
    gemm_mainloop(Ap, Bp, sm, KT64, tid, lane, wm, wn, acc);

    const int row0 = blockIdx.y * 128, col0 = blockIdx.x * 128;
#pragma unroll
    for (int mt = 0; mt < 2; mt++)
#pragma unroll
        for (int nt = 0; nt < 8; nt++) {
            int r = row0 + wm * 32 + mt * 16 + (lane >> 2);
            int cc = col0 + wn * 64 + nt * 8 + 2 * (lane & 3);
            *(float2*)&C[(size_t)r * N + cc] =
                make_float2(acc[mt][nt][0], acc[mt][nt][1]);
            *(float2*)&C[(size_t)(r + 8) * N + cc] =
                make_float2(acc[mt][nt][2], acc[mt][nt][3]);
        }
}

// ---------------------------------------------------------------------------
// QKV GEMM + fused RoPE + flash-layout fp16 packing epilogue (paired K/V).
// ---------------------------------------------------------------------------
__global__ __launch_bounds__(256, 2)
void gemm_qkv_rope(const unsigned* __restrict__ Apack, const unsigned* __restrict__ Bpack,
                   const int* __restrict__ pos,
                   unsigned* __restrict__ qp, unsigned* __restrict__ kpk,
                   unsigned* __restrict__ vp) {
    extern __shared__ unsigned sm[];
    const int tid = threadIdx.x;
    const int lane = tid & 31, wid = tid >> 5;
    const int wm = wid & 3, wn = wid >> 2;

    const unsigned* Ap = Apack + (size_t)blockIdx.y * 32 * 2048;
    const unsigned* Bp = Bpack + (size_t)blockIdx.x * 32 * 2048;

    float acc[2][8][4];
    gemm_mainloop(Ap, Bp, sm, DMODEL >> 6, tid, lane, wm, wn, acc);

    __half* vph = (__half*)vp;
    const int row0 = blockIdx.y * 128, col0 = blockIdx.x * 128;
#pragma unroll
    for (int mt = 0; mt < 2; mt++)
#pragma unroll
        for (int nt = 0; nt < 8; nt++) {
            int cg = col0 + wn * 64 + nt * 8 + 2 * (lane & 3);   // even
            int which = cg >> 10;
            int hh = (cg & 1023) >> 6;
            int d = cg & 63;                                      // even
#pragma unroll
            for (int half = 0; half < 2; half++) {
                int r = row0 + wm * 32 + mt * 16 + (lane >> 2) + half * 8;
                int b = r >> 11, sq = r & 2047;
                float v0 = acc[mt][nt][2 * half];
                float v1 = acc[mt][nt][2 * half + 1];
                if (which < 2) {
                    float p = (float)pos[r];
                    float inv = exp2f((float)d * -0.20762050593046f);
                    float ang = p * inv, sn, cs;
                    sincosf(ang, &sn, &cs);
                    float r0 = v0 * cs - v1 * sn;
                    float r1 = v0 * sn + v1 * cs;
                    if (which == 0) {
                        size_t base = ((size_t)(b * NHEADS + hh) * 16 + (sq >> 7)) * 4096;
                        qp[base + aw64h(sq & 127, d)] =
                            pack_h2(r0 * 0.125f, r1 * 0.125f);
                    } else {
                        size_t base = ((size_t)(b * NHEADS + hh) * 32 + (sq >> 6)) * 2048;
                        kpk[base + bw64h_p(sq & 63, d)] = pack_h2(r0, r1);
                    }
                } else {
                    size_t base = ((size_t)(b * NHEADS + hh) * 32 + (sq >> 6)) * 2048;
                    int kk = sq & 63;
                    vph[(base + bw64h_p(d, kk)) * 2 + (kk & 1)]     = __float2half_rn(v0);
                    vph[(base + bw64h_p(d + 1, kk)) * 2 + (kk & 1)] = __float2half_rn(v1);
                }
            }
        }
}

// ---------------------------------------------------------------------------
// Causal flash attention, fp16 mma, nt-paired K/V fragments.
// 6-stage KV ring, two tiles per wait+barrier, LPT grid.
// ---------------------------------------------------------------------------
#define FL_SMEM ((4096 + 6 * 4096) * 4)   // 112 KB

__global__ __launch_bounds__(256, 2)
void flash_packed(const unsigned* __restrict__ Qp, const unsigned* __restrict__ Kp,
                  const unsigned* __restrict__ Vp, unsigned* __restrict__ outp) {
    extern __shared__ unsigned sm[];
    unsigned* Qs = sm;
    unsigned* St = sm + 4096;

    const int bh = blockIdx.x;
    const int hh = bh & (NHEADS - 1);
    const int b  = bh >> 4;
    const int qb = gridDim.y - 1 - blockIdx.y;
    const int q0 = qb * 128;
    const int tid = threadIdx.x;
    const int lane = tid & 31, w = tid >> 5;
    const int qlane = lane & 3, grp = lane >> 2;

    const unsigned* qg = Qp + ((size_t)bh * 16 + qb) * 4096;
    const unsigned* kg = Kp + ((size_t)bh * 32) * 2048;
    const unsigned* vg = Vp + ((size_t)bh * 32) * 2048;

    const int ktiles = qb * 2 + 2;

#pragma unroll
    for (int i = 0; i < 4; i++) {
        int c = (tid + i * 256) * 4;
        cp_async16(Qs + c, qg + c);
    }
#pragma unroll
    for (int t = 0; t < 4; t++) {
        if (t < ktiles) {
            const unsigned* kgn = kg + (size_t)t * 2048;
            const unsigned* vgn = vg + (size_t)t * 2048;
            unsigned* dst = St + t * 4096;
#pragma unroll
            for (int i = 0; i < 2; i++) {
                int c = (tid + i * 256) * 4;
                cp_async16(dst + c, kgn + c);
                cp_async16(dst + 2048 + c, vgn + c);
            }
        }
        cp_commit();
    }

    float o[8][4];
#pragma unroll
    for (int nt = 0; nt < 8; nt++)
#pragma unroll
        for (int e = 0; e < 4; e++) o[nt][e] = 0.f;
    float m_run[2] = {-1e30f, -1e30f};
    float l_run[2] = {0.f, 0.f};

    const int rloc = w * 16 + grp;

    for (int kt = 0; kt < ktiles; kt += 2) {
        asm volatile("cp.async.wait_group 2;");
        __syncthreads();

#pragma unroll
        for (int t = 0; t < 2; t++) {
            int nk = kt + 4 + t;
            if (nk < ktiles) {
                const unsigned* kgn = kg + (size_t)nk * 2048;
                const unsigned* vgn = vg + (size_t)nk * 2048;
                unsigned* dst = St + (nk % 6) * 4096;
#pragma unroll
                for (int i = 0; i < 2; i++) {
                    int c = (tid + i * 256) * 4;
                    cp_async16(dst + c, kgn + c);
                    cp_async16(dst + 2048 + c, vgn + c);
                }
            }
            cp_commit();
        }

#pragma unroll
        for (int sub = 0; sub < 2; sub++) {
            const int kt2 = kt + sub;
            const int k0 = kt2 * 64;
            const unsigned* Ks = St + (kt2 % 6) * 4096;
            const unsigned* Vs = Ks + 2048;

            if (k0 <= q0 + w * 16 + 15) {
                // ---- S = Q K^T (nt-paired K: 4 x LDS.128 per ks) ----
                float s[8][4];
#pragma unroll
                for (int nt = 0; nt < 8; nt++)
#pragma unroll
                    for (int e = 0; e < 4; e++) s[nt][e] = 0.f;

#pragma unroll
                for (int ks = 0; ks < 4; ks++) {
                    unsigned qa[4];
                    *(uint4*)qa = *(const uint4*)&Qs[(w * 4 + ks) * 128 + lane * 4];
#pragma unroll
                    for (int nt2 = 0; nt2 < 4; nt2++) {
                        unsigned kq[4];
                        *(uint4*)kq = *(const uint4*)
                            &Ks[(nt2 * 4 + ks) * 128 + lane * 4];
                        mma16(s[2 * nt2],     qa, &kq[0]);
                        mma16(s[2 * nt2 + 1], qa, &kq[2]);
                    }
                }

                // ---- causal mask ----
                if (k0 + 63 > q0 + w * 16) {
                    int i0 = q0 + rloc;
#pragma unroll
                    for (int nt = 0; nt < 8; nt++) {
                        int j0 = k0 + nt * 8 + 2 * qlane;
                        if (j0 > i0)         s[nt][0] = -1e30f;
                        if (j0 + 1 > i0)     s[nt][1] = -1e30f;
                        if (j0 > i0 + 8)     s[nt][2] = -1e30f;
                        if (j0 + 1 > i0 + 8) s[nt][3] = -1e30f;
                    }
                }

                // ---- online softmax ----
                float alpha[2];
#pragma unroll
                for (int hrow = 0; hrow < 2; hrow++) {
                    float mx = -1e30f;
#pragma unroll
                    for (int nt = 0; nt < 8; nt++) {
                        mx = fmaxf(mx, s[nt][2 * hrow]);
                        mx = fmaxf(mx, s[nt][2 * hrow + 1]);
                    }
                    mx = fmaxf(mx, __shfl_xor_sync(0xffffffffu, mx, 1));
                    mx = fmaxf(mx, __shfl_xor_sync(0xffffffffu, mx, 2));
                    float mn = fmaxf(m_run[hrow], mx);
                    alpha[hrow] = __expf(m_run[hrow] - mn);
                    m_run[hrow] = mn;
                    float rs = 0.f;
#pragma unroll
                    for (int nt = 0; nt < 8; nt++) {
                        float p0 = __expf(s[nt][2 * hrow] - mn);
                        float p1 = __expf(s[nt][2 * hrow + 1] - mn);
                        s[nt][2 * hrow] = p0;
                        s[nt][2 * hrow + 1] = p1;
                        rs += p0 + p1;
                    }
                    rs += __shfl_xor_sync(0xffffffffu, rs, 1);
                    rs += __shfl_xor_sync(0xffffffffu, rs, 2);
                    l_run[hrow] = l_run[hrow] * alpha[hrow] + rs;
                }
#pragma unroll
                for (int nt = 0; nt < 8; nt++) {
                    o[nt][0] *= alpha[0]; o[nt][1] *= alpha[0];
                    o[nt][2] *= alpha[1]; o[nt][3] *= alpha[1];
                }

                // ---- O += P V (nt-paired V: 4 x LDS.128 per ks) ----
#pragma unroll
                for (int ks = 0; ks < 4; ks++) {
                    unsigned pa[4];
                    pa[0] = pack_h2(s[2 * ks][0],     s[2 * ks][1]);
                    pa[1] = pack_h2(s[2 * ks][2],     s[2 * ks][3]);
                    pa[2] = pack_h2(s[2 * ks + 1][0], s[2 * ks + 1][1]);
                    pa[3] = pack_h2(s[2 * ks + 1][2], s[2 * ks + 1][3]);
#pragma unroll
                    for (int nt2 = 0; nt2 < 4; nt2++) {
                        unsigned vq[4];
                        *(uint4*)vq = *(const uint4*)
                            &Vs[(nt2 * 4 + ks) * 128 + lane * 4];
                        mma16(o[2 * nt2],     pa, &vq[0]);
                        mma16(o[2 * nt2 + 1], pa, &vq[2]);
                    }
                }
            }
        }
    }

    // Epilogue: write fp16 A-frag16 tiles (out-proj A operand).
    float inv0 = 1.f / l_run[0];
    float inv1 = 1.f / l_run[1];
    const int rp = (b * SEQ + q0) >> 7;
#pragma unroll
    for (int nt = 0; nt < 8; nt++) {
        int c = hh * 64 + nt * 8 + 2 * qlane;
        int kp = c >> 5, kl = c & 31;
        size_t tb = ((size_t)rp * 32 + kp) * 2048;
        outp[tb + a_w16(rloc, kl)] =
            pack_h2(o[nt][0] * inv0, o[nt][1] * inv0);
        outp[tb + a_w16(rloc + 8, kl)] =
            pack_h2(o[nt][2] * inv1, o[nt][3] * inv1);
    }
}

// ---------------------------------------------------------------------------
// Launch
// ---------------------------------------------------------------------------
extern "C" void kernel_launch(void* const* d_in, const int* in_sizes, int n_in,
                              void* d_out, int out_size) {
    const float* x     = (const float*)d_in[0];
    const int*   pos   = (const int*)d_in[1];
    const float* w_qkv = (const float*)d_in[2];
    const float* w_o   = (const float*)d_in[3];
    float* out = (float*)d_out;

    unsigned *xp = nullptr, *wqp = nullptr, *wop = nullptr, *ap = nullptr;
    unsigned *qp = nullptr, *kp = nullptr, *vp = nullptr;
    cudaGetSymbolAddress((void**)&xp, g_xpack);
    cudaGetSymbolAddress((void**)&wqp, g_wqkv_pack);
    cudaGetSymbolAddress((void**)&wop, g_wo_pack);
    cudaGetSymbolAddress((void**)&ap, g_attn_pack);
    cudaGetSymbolAddress((void**)&qp, g_qpack);
    cudaGetSymbolAddress((void**)&kp, g_kpack);
    cudaGetSymbolAddress((void**)&vp, g_vpack);

    cudaFuncSetAttribute(gemm_packed,
                         cudaFuncAttributeMaxDynamicSharedMemorySize, GEMM_SMEM);
    cudaFuncSetAttribute(gemm_qkv_rope,
                         cudaFuncAttributeMaxDynamicSharedMemorySize, GEMM_SMEM);
    cudaFuncSetAttribute(flash_packed,
                         cudaFuncAttributeMaxDynamicSharedMemorySize, FL_SMEM);

    // 0) Pack all operands (single merged kernel)
    prep_kernel<<<(PA + PB1 + PB2 + 255) / 256, 256>>>(x, w_qkv, w_o, xp, wqp, wop);

    // 1) QKV projection + fused RoPE + flash-layout packing
    gemm_qkv_rope<<<dim3(3 * DMODEL / 128, MTOT / 128), 256, GEMM_SMEM>>>(
        xp, wqp, pos, qp, kp, vp);

    // 2) Flash attention (LPT grid)
    flash_packed<<<dim3(BATCH * NHEADS, SEQ / 128), 256, FL_SMEM>>>(qp, kp, vp, ap);

    // 3) Output projection
    gemm_packed<<<dim3(DMODEL / 128, MTOT / 128), 256, GEMM_SMEM>>>(
        ap, wop, out, MTOT, DMODEL, DMODEL);
}